// round 16
// baseline (speedup 1.0000x reference)
#include <cuda_runtime.h>
#include <math.h>

// Batched SIREN MLP: coords (B,N,2) f32, flat_weights (B,921) f32 -> (B,N,1) f32
// 2->20->20->20->1, hidden act sin(20*(Wx+b)), final clip [0,1].
//
// Numerics contract (R4-R15):
//  - dots: UNCONTRACTED scalar round(mul)+round(add), k ascending, acc from 0
//    (FMA contraction fails; packed f32x2 fails)
//  - +b, *20 separate rounded ops
//  - sine: pi-period magic-add reduction + odd deg-11 Taylor (abs err ~6e-8);
//    measured rel_err 8.07e-4 at this exact scheme
//
// Scheduling lessons: issue caps at ~86% for >=24 warps/SM; forcing regs to 64
// (4 blocks) adds ~100 alu shuffle slots and gains nothing (R15). R16 runs at
// natural register pressure and removes slots instead: bias loads vectorized
// (groups of 4 outputs share one LDS.128 bias fetch; load width only — the
// FP sequence is bit-identical to R15).

#define HID 20
#define PSZ 921

// Branch-free sine via pi-reduction. |x| <= ~3000. Abs err ~6e-8.
__device__ __forceinline__ float sin_fast(float x) {
    constexpr float  INV_PI = 0.31830988618379067154f;
    constexpr float  MAGIC = 12582912.0f;  // 1.5 * 2^23
    constexpr double PID = 3.14159265358979323846264338328;
    constexpr float  PI1 = (float)PID;
    constexpr float  PI2 = (float)(PID - (double)PI1);

    float t = fmaf(x, INV_PI, MAGIC);
    unsigned q = __float_as_uint(t);        // low bit == k mod 2
    float kf = t - MAGIC;

    float r = fmaf(-kf, PI1, x);
    r = fmaf(-kf, PI2, r);

    float z = r * r;

    // sin(r), odd poly through r^11 (trunc err ~5.7e-8 at pi/2)
    float p = fmaf(z, -2.50521083854417188e-8f,  2.75573192239858907e-6f);
    p = fmaf(z, p, -1.98412698412698413e-4f);
    p = fmaf(z, p,  8.33333333333333322e-3f);
    p = fmaf(z, p, -1.66666666666666667e-1f);
    float sinv = fmaf(r * z, p, r);

    return __uint_as_float(__float_as_uint(sinv) ^ (q << 31));
}

__global__ __launch_bounds__(256) void siren_kernel(
    const float* __restrict__ coords,
    const float* __restrict__ weights,
    float* __restrict__ out,
    int N)
{
    __shared__ __align__(16) float s[PSZ];
    const int b = blockIdx.y;

    const float* wb = weights + (size_t)b * PSZ;
    for (int i = threadIdx.x; i < PSZ; i += blockDim.x) s[i] = wb[i];
    __syncthreads();

    const int n = blockIdx.x * blockDim.x + threadIdx.x;
    if (n >= N) return;

    const float2 c =
        reinterpret_cast<const float2*>(coords + (size_t)b * (size_t)N * 2)[n];

    float a0[HID];
    float a1[HID];

    // ---- Layer 1: 2 -> 20 ---- groups of 4 outputs: 2x LDS.128 weights +
    // 1x LDS.128 biases. (weights at s[0..39], biases at s[40..59], 16B aligned)
    #pragma unroll
    for (int g = 0; g < HID / 4; g++) {
        float4 wA = *reinterpret_cast<const float4*>(&s[8 * g]);      // w for o=4g,4g+1
        float4 wB = *reinterpret_cast<const float4*>(&s[8 * g + 4]);  // w for o=4g+2,4g+3
        float4 bias = *reinterpret_cast<const float4*>(&s[40 + 4 * g]);
        float t0 = __fadd_rn(__fmul_rn(wA.x, c.x), __fmul_rn(wA.y, c.y));
        float t1 = __fadd_rn(__fmul_rn(wA.z, c.x), __fmul_rn(wA.w, c.y));
        float t2 = __fadd_rn(__fmul_rn(wB.x, c.x), __fmul_rn(wB.y, c.y));
        float t3 = __fadd_rn(__fmul_rn(wB.z, c.x), __fmul_rn(wB.w, c.y));
        a0[4 * g + 0] = sin_fast(__fmul_rn(20.0f, __fadd_rn(t0, bias.x)));
        a0[4 * g + 1] = sin_fast(__fmul_rn(20.0f, __fadd_rn(t1, bias.y)));
        a0[4 * g + 2] = sin_fast(__fmul_rn(20.0f, __fadd_rn(t2, bias.z)));
        a0[4 * g + 3] = sin_fast(__fmul_rn(20.0f, __fadd_rn(t3, bias.w)));
    }

    // ---- Layer 2: 20 -> 20 ---- groups of 4 outputs share one bias LDS.128
    #pragma unroll
    for (int g = 0; g < HID / 4; g++) {
        float4 bias = *reinterpret_cast<const float4*>(&s[460 + 4 * g]);
        #pragma unroll
        for (int oo = 0; oo < 4; oo++) {
            int o = 4 * g + oo;
            const float4* wrow = reinterpret_cast<const float4*>(&s[60 + o * HID]);
            float acc = 0.0f;
            #pragma unroll
            for (int v = 0; v < HID / 4; v++) {
                float4 w = wrow[v];
                acc = __fadd_rn(acc, __fmul_rn(w.x, a0[4 * v + 0]));
                acc = __fadd_rn(acc, __fmul_rn(w.y, a0[4 * v + 1]));
                acc = __fadd_rn(acc, __fmul_rn(w.z, a0[4 * v + 2]));
                acc = __fadd_rn(acc, __fmul_rn(w.w, a0[4 * v + 3]));
            }
            float bv = (oo == 0) ? bias.x : (oo == 1) ? bias.y : (oo == 2) ? bias.z : bias.w;
            acc = __fadd_rn(acc, bv);
            a1[o] = sin_fast(__fmul_rn(20.0f, acc));
        }
    }

    // ---- Layer 3: 20 -> 20 ----
    #pragma unroll
    for (int g = 0; g < HID / 4; g++) {
        float4 bias = *reinterpret_cast<const float4*>(&s[880 + 4 * g]);
        #pragma unroll
        for (int oo = 0; oo < 4; oo++) {
            int o = 4 * g + oo;
            const float4* wrow = reinterpret_cast<const float4*>(&s[480 + o * HID]);
            float acc = 0.0f;
            #pragma unroll
            for (int v = 0; v < HID / 4; v++) {
                float4 w = wrow[v];
                acc = __fadd_rn(acc, __fmul_rn(w.x, a1[4 * v + 0]));
                acc = __fadd_rn(acc, __fmul_rn(w.y, a1[4 * v + 1]));
                acc = __fadd_rn(acc, __fmul_rn(w.z, a1[4 * v + 2]));
                acc = __fadd_rn(acc, __fmul_rn(w.w, a1[4 * v + 3]));
            }
            float bv = (oo == 0) ? bias.x : (oo == 1) ? bias.y : (oo == 2) ? bias.z : bias.w;
            acc = __fadd_rn(acc, bv);
            a0[o] = sin_fast(__fmul_rn(20.0f, acc));
        }
    }

    // ---- Layer 4: 20 -> 1, clip ----
    {
        const float4* wrow = reinterpret_cast<const float4*>(&s[900]);
        float acc = 0.0f;
        #pragma unroll
        for (int v = 0; v < HID / 4; v++) {
            float4 w = wrow[v];
            acc = __fadd_rn(acc, __fmul_rn(w.x, a0[4 * v + 0]));
            acc = __fadd_rn(acc, __fmul_rn(w.y, a0[4 * v + 1]));
            acc = __fadd_rn(acc, __fmul_rn(w.z, a0[4 * v + 2]));
            acc = __fadd_rn(acc, __fmul_rn(w.w, a0[4 * v + 3]));
        }
        acc = __fadd_rn(acc, s[920]);
        out[(size_t)b * (size_t)N + n] = fminf(fmaxf(acc, 0.0f), 1.0f);
    }
}

extern "C" void kernel_launch(void* const* d_in, const int* in_sizes, int n_in,
                              void* d_out, int out_size) {
    const float* coords  = (const float*)d_in[0];   // (B, N, 2)
    const float* weights = (const float*)d_in[1];   // (B, 921)
    float* out = (float*)d_out;                     // (B, N, 1)

    const int B = in_sizes[1] / PSZ;
    const int N = in_sizes[0] / (2 * B);

    dim3 block(256);
    dim3 grid((N + 255) / 256, B);
    siren_kernel<<<grid, block>>>(coords, weights, out, N);
}

// round 17
// speedup vs baseline: 1.6139x; 1.6139x over previous
#include <cuda_runtime.h>
#include <math.h>

// Batched SIREN MLP: coords (B,N,2) f32, flat_weights (B,921) f32 -> (B,N,1) f32
// 2->20->20->20->1, hidden act sin(20*(Wx+b)), final clip [0,1].
//
// Numerics contract (R4-R16):
//  - dots: UNCONTRACTED scalar round(mul)+round(add), k ascending, acc from 0
//    (FMA contraction fails; packed f32x2 fails)
//  - +b, *20 separate rounded ops
//  - sine: pi-period magic-add reduction + odd deg-11 Taylor (abs err ~6e-8);
//    this exact scheme measured at rel_err 8.067586e-4 (R15/R16)
//
// Codegen contract (R15/R16 lessons): no forced register budgets, no nested
// loop restructures — this is R14's exact body (741.9us, the measured best)
// with ONLY the sine poly trimmed deg-13 -> deg-11.

#define HID 20
#define PSZ 921

// Branch-free sine via pi-reduction. |x| <= ~3000. Abs err ~6e-8.
__device__ __forceinline__ float sin_fast(float x) {
    constexpr float  INV_PI = 0.31830988618379067154f;
    constexpr float  MAGIC = 12582912.0f;  // 1.5 * 2^23
    constexpr double PID = 3.14159265358979323846264338328;
    constexpr float  PI1 = (float)PID;
    constexpr float  PI2 = (float)(PID - (double)PI1);

    float t = fmaf(x, INV_PI, MAGIC);
    unsigned q = __float_as_uint(t);        // low bit == k mod 2
    float kf = t - MAGIC;

    float r = fmaf(-kf, PI1, x);
    r = fmaf(-kf, PI2, r);

    float z = r * r;

    // sin(r), odd poly through r^11 (trunc err ~5.7e-8 at pi/2)
    float p = fmaf(z, -2.50521083854417188e-8f,  2.75573192239858907e-6f);
    p = fmaf(z, p, -1.98412698412698413e-4f);
    p = fmaf(z, p,  8.33333333333333322e-3f);
    p = fmaf(z, p, -1.66666666666666667e-1f);
    float sinv = fmaf(r * z, p, r);

    return __uint_as_float(__float_as_uint(sinv) ^ (q << 31));
}

__global__ __launch_bounds__(256) void siren_kernel(
    const float* __restrict__ coords,
    const float* __restrict__ weights,
    float* __restrict__ out,
    int N)
{
    __shared__ __align__(16) float s[PSZ];
    const int b = blockIdx.y;

    const float* wb = weights + (size_t)b * PSZ;
    for (int i = threadIdx.x; i < PSZ; i += blockDim.x) s[i] = wb[i];
    __syncthreads();

    const int n = blockIdx.x * blockDim.x + threadIdx.x;
    if (n >= N) return;

    const float2 c =
        reinterpret_cast<const float2*>(coords + (size_t)b * (size_t)N * 2)[n];

    float a0[HID];
    float a1[HID];

    // ---- Layer 1: 2 -> 20 ---- (LDS.128 covers weights for 2 outputs)
    #pragma unroll
    for (int o2 = 0; o2 < HID / 2; o2++) {
        float4 w = *reinterpret_cast<const float4*>(&s[4 * o2]);
        int oA = 2 * o2, oB = 2 * o2 + 1;
        float accA = __fadd_rn(__fmul_rn(w.x, c.x), __fmul_rn(w.y, c.y));
        float accB = __fadd_rn(__fmul_rn(w.z, c.x), __fmul_rn(w.w, c.y));
        accA = __fadd_rn(accA, s[40 + oA]);
        accB = __fadd_rn(accB, s[40 + oB]);
        a0[oA] = sin_fast(__fmul_rn(20.0f, accA));
        a0[oB] = sin_fast(__fmul_rn(20.0f, accB));
    }

    // ---- Layer 2: 20 -> 20 ---- (sequential uncontracted; LDS.128 weights)
    #pragma unroll
    for (int o = 0; o < HID; o++) {
        const float4* wrow = reinterpret_cast<const float4*>(&s[60 + o * HID]);
        float acc = 0.0f;
        #pragma unroll
        for (int v = 0; v < HID / 4; v++) {
            float4 w = wrow[v];
            acc = __fadd_rn(acc, __fmul_rn(w.x, a0[4 * v + 0]));
            acc = __fadd_rn(acc, __fmul_rn(w.y, a0[4 * v + 1]));
            acc = __fadd_rn(acc, __fmul_rn(w.z, a0[4 * v + 2]));
            acc = __fadd_rn(acc, __fmul_rn(w.w, a0[4 * v + 3]));
        }
        acc = __fadd_rn(acc, s[460 + o]);
        a1[o] = sin_fast(__fmul_rn(20.0f, acc));
    }

    // ---- Layer 3: 20 -> 20 ----
    #pragma unroll
    for (int o = 0; o < HID; o++) {
        const float4* wrow = reinterpret_cast<const float4*>(&s[480 + o * HID]);
        float acc = 0.0f;
        #pragma unroll
        for (int v = 0; v < HID / 4; v++) {
            float4 w = wrow[v];
            acc = __fadd_rn(acc, __fmul_rn(w.x, a1[4 * v + 0]));
            acc = __fadd_rn(acc, __fmul_rn(w.y, a1[4 * v + 1]));
            acc = __fadd_rn(acc, __fmul_rn(w.z, a1[4 * v + 2]));
            acc = __fadd_rn(acc, __fmul_rn(w.w, a1[4 * v + 3]));
        }
        acc = __fadd_rn(acc, s[880 + o]);
        a0[o] = sin_fast(__fmul_rn(20.0f, acc));
    }

    // ---- Layer 4: 20 -> 1, clip ----
    {
        const float4* wrow = reinterpret_cast<const float4*>(&s[900]);
        float acc = 0.0f;
        #pragma unroll
        for (int v = 0; v < HID / 4; v++) {
            float4 w = wrow[v];
            acc = __fadd_rn(acc, __fmul_rn(w.x, a0[4 * v + 0]));
            acc = __fadd_rn(acc, __fmul_rn(w.y, a0[4 * v + 1]));
            acc = __fadd_rn(acc, __fmul_rn(w.z, a0[4 * v + 2]));
            acc = __fadd_rn(acc, __fmul_rn(w.w, a0[4 * v + 3]));
        }
        acc = __fadd_rn(acc, s[920]);
        out[(size_t)b * (size_t)N + n] = fminf(fmaxf(acc, 0.0f), 1.0f);
    }
}

extern "C" void kernel_launch(void* const* d_in, const int* in_sizes, int n_in,
                              void* d_out, int out_size) {
    const float* coords  = (const float*)d_in[0];   // (B, N, 2)
    const float* weights = (const float*)d_in[1];   // (B, 921)
    float* out = (float*)d_out;                     // (B, N, 1)

    const int B = in_sizes[1] / PSZ;
    const int N = in_sizes[0] / (2 * B);

    dim3 block(256);
    dim3 grid((N + 255) / 256, B);
    siren_kernel<<<grid, block>>>(coords, weights, out, N);
}